// round 8
// baseline (speedup 1.0000x reference)
#include <cuda_runtime.h>

#define BATCH 32
#define LC 512
#define LQ 64
#define DIM 1024

typedef unsigned long long u64;

__device__ __forceinline__ u64 ffma2(u64 a, u64 b, u64 c) {
    u64 d;
    asm("fma.rn.f32x2 %0, %1, %2, %3;" : "=l"(d) : "l"(a), "l"(b), "l"(c));
    return d;
}
__device__ __forceinline__ float pairsum(u64 v) {
    float2 r;
    asm("mov.b64 {%0, %1}, %2;" : "=f"(r.x), "=f"(r.y) : "l"(v));
    return r.x + r.y;
}
__device__ __forceinline__ void cp16(unsigned saddr, const void* gaddr) {
    asm volatile("cp.async.cg.shared.global [%0], [%1], 16;"
                 :: "r"(saddr), "l"(gaddr) : "memory");
}
#define CP_COMMIT() asm volatile("cp.async.commit_group;" ::: "memory")
#define CP_WAIT1()  asm volatile("cp.async.wait_group 1;" ::: "memory")

// ---------------- scratch -----------------------------------------------------
__device__ float g_s0[BATCH * LC];          // c @ proj_c
__device__ float g_s1[BATCH * LQ];          // q @ proj_q
__device__ float g_qs[BATCH * LQ * DIM];    // q * proj_cq (8 MiB)
__device__ float g_sim[BATCH * LC * LQ];    // similarity matrix (4 MiB)
__device__ float g_m[BATCH * LC];           // rowmax of sim over q
__device__ float g_q2c[BATCH * DIM];        // query-to-context vector

// ---------------- K0: projections + scaled q + zero q2c ---------------------
__global__ void k_pre(const float* __restrict__ c, const float* __restrict__ q,
                      const float* __restrict__ pc, const float* __restrict__ pq,
                      const float* __restrict__ pcq) {
    int gtid = blockIdx.x * blockDim.x + threadIdx.x;
    if (gtid < BATCH * DIM) g_q2c[gtid] = 0.f;

    int warp = gtid >> 5;
    int lane = threadIdx.x & 31;
    const int NC = BATCH * LC;
    if (warp < NC) {
        const float* src = c + (size_t)warp * DIM;
        float s = 0.f;
#pragma unroll
        for (int i = 0; i < 8; i++) {
            int k = (lane + i * 32) * 4;
            float4 v = *(const float4*)(src + k);
            float4 p = *(const float4*)(pc + k);
            s += v.x * p.x + v.y * p.y + v.z * p.z + v.w * p.w;
        }
#pragma unroll
        for (int o = 16; o; o >>= 1) s += __shfl_xor_sync(0xffffffffu, s, o);
        if (lane == 0) g_s0[warp] = s;
    } else if (warp < NC + BATCH * LQ) {
        int r = warp - NC;
        const float* src = q + (size_t)r * DIM;
        float* dst = g_qs + (size_t)r * DIM;
        float s = 0.f;
#pragma unroll
        for (int i = 0; i < 8; i++) {
            int k = (lane + i * 32) * 4;
            float4 v  = *(const float4*)(src + k);
            float4 pp = *(const float4*)(pq + k);
            s += v.x * pp.x + v.y * pp.y + v.z * pp.z + v.w * pp.w;
            float4 pv = *(const float4*)(pcq + k);
            float4 o = {v.x * pv.x, v.y * pv.y, v.z * pv.z, v.w * pv.w};
            *(float4*)(dst + k) = o;
        }
#pragma unroll
        for (int o = 16; o; o >>= 1) s += __shfl_xor_sync(0xffffffffu, s, o);
        if (lane == 0) g_s1[r] = s;
    }
}

// ---------------- K1: sim GEMM: sim = c @ qs^T + s0 + s1 ; rowmax -----------
// tile 32(m)x64(n), 128 threads, micro 4x4, f32x2 K-pairs via LDS.128,
// cp.async double buffer, grid (16, 32) = 512 blocks, 6 CTAs/SM.
#define KT 32
#define AW 36
__global__ void __launch_bounds__(128, 6)
k_sim(const float* __restrict__ c) {
    __shared__ __align__(16) float As[2][32][AW];   // 9 KB
    __shared__ __align__(16) float Bs[2][64][AW];   // 18 KB

    int b = blockIdx.y, cm = blockIdx.x;
    int tl = threadIdx.x;
    int tx = tl & 15;          // n-thread
    int ty = tl >> 4;          // m-thread (0..7)

    const float* cA = c + ((size_t)b * LC + cm * 32) * DIM;
    const float* cB = g_qs + (size_t)b * LQ * DIM;

    int lrow = tl >> 3;             // 0..15
    int lkp = (tl & 7) * 4;         // 0..28
    const float* gA0 = cA + (size_t)lrow * DIM + lkp;
    const float* gB0 = cB + (size_t)lrow * DIM + lkp;
    unsigned saA = (unsigned)__cvta_generic_to_shared(&As[0][lrow][lkp]);
    unsigned saB = (unsigned)__cvta_generic_to_shared(&Bs[0][lrow][lkp]);
    const unsigned SA = 32 * AW * 4;
    const unsigned SB = 64 * AW * 4;
    const unsigned R16 = 16 * AW * 4;

    u64 acc[4][4];
#pragma unroll
    for (int i = 0; i < 4; i++)
#pragma unroll
        for (int j = 0; j < 4; j++) acc[i][j] = 0ull;

    cp16(saA, gA0);
    cp16(saA + R16, gA0 + 16 * DIM);
#pragma unroll
    for (int i = 0; i < 4; i++)
        cp16(saB + i * R16, gB0 + (size_t)(16 * i) * DIM);
    CP_COMMIT();

    for (int it = 0; it < DIM / KT; it++) {
        int nit = (it + 1 < DIM / KT) ? it + 1 : it;
        unsigned nb = (it + 1) & 1;
        cp16(saA + nb * SA, gA0 + nit * KT);
        cp16(saA + nb * SA + R16, gA0 + 16 * DIM + nit * KT);
#pragma unroll
        for (int i = 0; i < 4; i++)
            cp16(saB + nb * SB + i * R16, gB0 + (size_t)(16 * i) * DIM + nit * KT);
        CP_COMMIT();
        CP_WAIT1();
        __syncthreads();

        int pp = it & 1;
#pragma unroll
        for (int kk4 = 0; kk4 < KT / 4; kk4++) {
            ulonglong2 am[4], bn[4];
#pragma unroll
            for (int i = 0; i < 4; i++)
                am[i] = *(const ulonglong2*)&As[pp][ty + 8 * i][kk4 * 4];
#pragma unroll
            for (int j = 0; j < 4; j++)
                bn[j] = *(const ulonglong2*)&Bs[pp][tx + 16 * j][kk4 * 4];
#pragma unroll
            for (int i = 0; i < 4; i++)
#pragma unroll
                for (int j = 0; j < 4; j++) {
                    acc[i][j] = ffma2(am[i].x, bn[j].x, acc[i][j]);
                    acc[i][j] = ffma2(am[i].y, bn[j].y, acc[i][j]);
                }
        }
        __syncthreads();
    }

    // epilogue: add s0+s1, rowmax over 16 tx lanes, stage, coalesced write
    float (*sim_s)[68] = (float(*)[68])&As[0][0][0];
    float s1v[4];
#pragma unroll
    for (int j = 0; j < 4; j++) s1v[j] = g_s1[b * LQ + tx + 16 * j];
#pragma unroll
    for (int i = 0; i < 4; i++) {
        int m = ty + 8 * i;
        float s0v = g_s0[b * LC + cm * 32 + m];
        float rm = -3.4e38f;
        float vals[4];
#pragma unroll
        for (int j = 0; j < 4; j++) {
            vals[j] = pairsum(acc[i][j]) + s0v + s1v[j];
            rm = fmaxf(rm, vals[j]);
        }
#pragma unroll
        for (int o = 8; o; o >>= 1) rm = fmaxf(rm, __shfl_xor_sync(0xffffffffu, rm, o));
#pragma unroll
        for (int j = 0; j < 4; j++) sim_s[m][tx + 16 * j] = vals[j];
        if (tx == 0) g_m[b * LC + cm * 32 + m] = rm;
    }
    __syncthreads();

#pragma unroll
    for (int i = 0; i < 4; i++) {
        int idx = tl + 128 * i;
        int wrow = idx >> 4;
        int wcol = (idx & 15) * 4;
        *(float4*)&g_sim[((size_t)b * LC + cm * 32 + wrow) * LQ + wcol] =
            *(const float4*)&sim_s[wrow][wcol];
    }
}

// ---------------- K2: q2c[b,:] = softmax_c(m) @ c[b] ------------------------
// grid (64, B) = 2048 blocks, 8 c-rows per block, MLP 8
__global__ void k_q2c(const float* __restrict__ c) {
    __shared__ float wm[LC];
    __shared__ float red[256];
    int b = blockIdx.y, cb = blockIdx.x;
    int t = threadIdx.x;
    float v0 = g_m[b * LC + t];
    float v1 = g_m[b * LC + 256 + t];
    red[t] = fmaxf(v0, v1);
    __syncthreads();
#pragma unroll
    for (int s = 128; s > 0; s >>= 1) {
        if (t < s) red[t] = fmaxf(red[t], red[t + s]);
        __syncthreads();
    }
    float mx = red[0];
    __syncthreads();
    float e0 = expf(v0 - mx), e1 = expf(v1 - mx);
    wm[t] = e0;
    wm[t + 256] = e1;
    red[t] = e0 + e1;
    __syncthreads();
#pragma unroll
    for (int s = 128; s > 0; s >>= 1) {
        if (t < s) red[t] += red[t + s];
        __syncthreads();
    }
    float inv = 1.f / red[0];
    __syncthreads();

    float4 acc = {0.f, 0.f, 0.f, 0.f};
    const float* cb0 = c + ((size_t)b * LC + cb * 8) * DIM + (t << 2);
#pragma unroll
    for (int cr = 0; cr < 8; cr++) {
        float w = wm[cb * 8 + cr] * inv;
        float4 cv = *(const float4*)(cb0 + (size_t)cr * DIM);
        acc.x = fmaf(w, cv.x, acc.x);
        acc.y = fmaf(w, cv.y, acc.y);
        acc.z = fmaf(w, cv.z, acc.z);
        acc.w = fmaf(w, cv.w, acc.w);
    }
    float* dst = g_q2c + b * DIM + (t << 2);
    atomicAdd(dst + 0, acc.x);
    atomicAdd(dst + 1, acc.y);
    atomicAdd(dst + 2, acc.z);
    atomicAdd(dst + 3, acc.w);
}

// ---------------- K3: softmax rows, c2q = a @ q (qq-paired f32x2), output ---
// grid (LC/RT, DIM/DQ, BATCH) = (8, 4, 32) = 1024 blocks, 256 threads.
// a in qq-pairs (broadcast LDS.128), q transposed to qq-pairs at chunk fill.
#define RT 64
#define DQ 256
#define DC 128
#define APW 132   // a_p row stride (floats): 64 pairs*2 + 4 pad, 16B multiple
#define QPW 264   // q_p row stride (floats): 128 pairs*2 + 8 pad, 16B multiple
__global__ void __launch_bounds__(256, 2)
k_out(const float* __restrict__ c, const float* __restrict__ q,
      float* __restrict__ out) {
    __shared__ __align__(16) float a_p[32][APW];   // 16.5 KB: [qq/2][2r+(qq&1)]
    __shared__ __align__(16) float q_p[32][QPW];   // 33 KB:  [qq/2][2d+(qq&1)]
    int ct = blockIdx.x, dqi = blockIdx.y, b = blockIdx.z;
    int t = threadIdx.x;
    int warp = t >> 5, lane = t & 31;
    int rbase = warp * 8;

    // row softmax from stored rowmax; write as qq-pairs
#pragma unroll
    for (int i = 0; i < 8; i++) {
        int r = warp * 8 + i;
        int row = ct * RT + r;
        size_t sbase = ((size_t)b * LC + row) * LQ;
        float m = g_m[b * LC + row];
        float v0 = expf(g_sim[sbase + lane] - m);
        float v1 = expf(g_sim[sbase + lane + 32] - m);
        float s = v0 + v1;
#pragma unroll
        for (int o = 16; o; o >>= 1) s += __shfl_xor_sync(0xffffffffu, s, o);
        float inv = 1.f / s;
        a_p[lane >> 1][2 * r + (lane & 1)] = v0 * inv;
        a_p[16 + (lane >> 1)][2 * r + (lane & 1)] = v1 * inv;
    }
    __syncthreads();

    const float* qb = q + (size_t)b * LQ * DIM;
    int dq0 = dqi * DQ;

    for (int dc = dq0; dc < dq0 + DQ; dc += DC) {
        // fill q_p: qq-paired transpose built in registers, STS.128 out
#pragma unroll
        for (int i = 0; i < 4; i++) {
            int idx = t + i * 256;          // 0..1023
            int qp = idx >> 5;              // 0..31
            int d4 = idx & 31;
            const float* g0 = qb + (size_t)(2 * qp) * DIM + dc + d4 * 4;
            float4 f0 = *(const float4*)(g0);
            float4 f1 = *(const float4*)(g0 + DIM);
            float4 s0 = {f0.x, f1.x, f0.y, f1.y};
            float4 s1 = {f0.z, f1.z, f0.w, f1.w};
            *(float4*)&q_p[qp][d4 * 8] = s0;
            *(float4*)&q_p[qp][d4 * 8 + 4] = s1;
        }
        __syncthreads();

        u64 acc[8][4];
#pragma unroll
        for (int r = 0; r < 8; r++)
#pragma unroll
            for (int d = 0; d < 4; d++) acc[r][d] = 0ull;

#pragma unroll 4
        for (int qp = 0; qp < 32; qp++) {
            ulonglong2 a01 = *(const ulonglong2*)&a_p[qp][2 * rbase];
            ulonglong2 a23 = *(const ulonglong2*)&a_p[qp][2 * rbase + 4];
            ulonglong2 a45 = *(const ulonglong2*)&a_p[qp][2 * rbase + 8];
            ulonglong2 a67 = *(const ulonglong2*)&a_p[qp][2 * rbase + 12];
            ulonglong2 q01 = *(const ulonglong2*)&q_p[qp][lane * 8];
            ulonglong2 q23 = *(const ulonglong2*)&q_p[qp][lane * 8 + 4];
            u64 ar[8] = {a01.x, a01.y, a23.x, a23.y, a45.x, a45.y, a67.x, a67.y};
            u64 qd[4] = {q01.x, q01.y, q23.x, q23.y};
#pragma unroll
            for (int r = 0; r < 8; r++)
#pragma unroll
                for (int d = 0; d < 4; d++)
                    acc[r][d] = ffma2(ar[r], qd[d], acc[r][d]);
        }

        int d0 = dc + (lane << 2);
        float4 qc4 = *(const float4*)(g_q2c + b * DIM + d0);
#pragma unroll
        for (int r = 0; r < 8; r++) {
            float4 a4 = {pairsum(acc[r][0]), pairsum(acc[r][1]),
                         pairsum(acc[r][2]), pairsum(acc[r][3])};
            int row = ct * RT + rbase + r;
            float4 cv = *(const float4*)(c + ((size_t)b * LC + row) * DIM + d0);
            float* ob = out + ((size_t)b * LC + row) * (4 * DIM) + d0;
            *(float4*)(ob) = cv;
            *(float4*)(ob + DIM) = a4;
            float4 t2 = {cv.x * qc4.x, cv.y * qc4.y, cv.z * qc4.z, cv.w * qc4.w};
            *(float4*)(ob + 2 * DIM) = t2;
            float4 t3 = {cv.x * a4.x, cv.y * a4.y, cv.z * a4.z, cv.w * a4.w};
            *(float4*)(ob + 3 * DIM) = t3;
        }
        __syncthreads();
    }
}

// ---------------- launch -----------------------------------------------------
extern "C" void kernel_launch(void* const* d_in, const int* in_sizes, int n_in,
                              void* d_out, int out_size) {
    const float* c   = (const float*)d_in[0];
    const float* q   = (const float*)d_in[1];
    const float* pc  = (const float*)d_in[2];
    const float* pq  = (const float*)d_in[3];
    const float* pcq = (const float*)d_in[4];
    float* out = (float*)d_out;
    (void)in_sizes; (void)n_in; (void)out_size;

    k_pre<<<BATCH * (LC + LQ) * 32 / 256, 256>>>(c, q, pc, pq, pcq);
    k_sim<<<dim3(LC / 32, BATCH), 128>>>(c);
    k_q2c<<<dim3(64, BATCH), 256>>>(c);
    k_out<<<dim3(LC / RT, DIM / DQ, BATCH), 256>>>(c, q, out);
}